// round 6
// baseline (speedup 1.0000x reference)
#include <cuda_runtime.h>
#include <math.h>

#define B_ 8
#define S_ 1024
#define D_ 256
#define H_ 8
#define DH_ 32
#define BH_ (B_*H_)
#define ROWS 16
#define JC 256
#define SS_STRIDE 1028
#define THREADS 512

// Scratch (device globals: no allocation allowed)
__device__ float g_Qp[BH_*S_*DH_];   // [B,H,S,DH]
__device__ float g_Kp[BH_*S_*DH_];
__device__ float g_Vp[BH_*S_*DH_];
__device__ float g_ctx[B_*S_*D_];    // attention output, [B,S,D]

// ---------------------------------------------------------------------------
// GEMM body: C[m,n] = sum_k A[m,k]*W[n,k] + bias[n]; 128x128 tile, 8x8 micro
// ---------------------------------------------------------------------------
__device__ __forceinline__ void gemm_body(
    const float* __restrict__ A, const float* __restrict__ W,
    const float* __restrict__ bias, float* __restrict__ C, int headLayout)
{
    __shared__ float sA[16][132];
    __shared__ float sW[16][132];
    const int K = D_;
    int tid = threadIdx.x;
    int tx = tid & 15, ty = tid >> 4;            // 16x16 thread grid
    int m0 = blockIdx.y * 128, n0 = blockIdx.x * 128;
    int lr = tid >> 2, lc = (tid & 3) * 4;       // staging: rows lr, lr+64
    float acc[8][8] = {};
    for (int k0 = 0; k0 < K; k0 += 16) {
        float4 a0 = *(const float4*)&A[(size_t)(m0 + lr) * K + k0 + lc];
        float4 a1 = *(const float4*)&A[(size_t)(m0 + lr + 64) * K + k0 + lc];
        float4 w0 = *(const float4*)&W[(size_t)(n0 + lr) * K + k0 + lc];
        float4 w1 = *(const float4*)&W[(size_t)(n0 + lr + 64) * K + k0 + lc];
        sA[lc+0][lr] = a0.x; sA[lc+1][lr] = a0.y; sA[lc+2][lr] = a0.z; sA[lc+3][lr] = a0.w;
        sA[lc+0][lr+64] = a1.x; sA[lc+1][lr+64] = a1.y; sA[lc+2][lr+64] = a1.z; sA[lc+3][lr+64] = a1.w;
        sW[lc+0][lr] = w0.x; sW[lc+1][lr] = w0.y; sW[lc+2][lr] = w0.z; sW[lc+3][lr] = w0.w;
        sW[lc+0][lr+64] = w1.x; sW[lc+1][lr+64] = w1.y; sW[lc+2][lr+64] = w1.z; sW[lc+3][lr+64] = w1.w;
        __syncthreads();
        #pragma unroll
        for (int kk = 0; kk < 16; kk++) {
            float4 alo = *(const float4*)&sA[kk][ty*8];
            float4 ahi = *(const float4*)&sA[kk][ty*8+4];
            float4 blo = *(const float4*)&sW[kk][tx*8];
            float4 bhi = *(const float4*)&sW[kk][tx*8+4];
            float a[8] = {alo.x, alo.y, alo.z, alo.w, ahi.x, ahi.y, ahi.z, ahi.w};
            float bb[8] = {blo.x, blo.y, blo.z, blo.w, bhi.x, bhi.y, bhi.z, bhi.w};
            #pragma unroll
            for (int i = 0; i < 8; i++)
                #pragma unroll
                for (int j = 0; j < 8; j++)
                    acc[i][j] = fmaf(a[i], bb[j], acc[i][j]);
        }
        __syncthreads();
    }
    #pragma unroll
    for (int i = 0; i < 8; i++) {
        int m = m0 + ty*8 + i;
        int bbat = m >> 10, ss = m & 1023;
        #pragma unroll
        for (int j = 0; j < 8; j++) {
            int n = n0 + tx*8 + j;
            float val = acc[i][j] + bias[n];
            if (headLayout) {
                int h = n >> 5, dh = n & 31;
                C[(((size_t)(bbat*H_ + h) * S_) + ss) * DH_ + dh] = val;
            } else {
                C[(size_t)m * D_ + n] = val;
            }
        }
    }
}

// 3 projection GEMMs in one launch (z selects)
__global__ __launch_bounds__(256, 2) void proj3_kernel(
    const float* __restrict__ q, const float* __restrict__ k, const float* __restrict__ v,
    const float* __restrict__ Wq, const float* __restrict__ bq,
    const float* __restrict__ Wv, const float* __restrict__ bv,
    float* __restrict__ Qp, float* __restrict__ Kp, float* __restrict__ Vp)
{
    int z = blockIdx.z;
    const float* A = (z == 0) ? q : (z == 1) ? k : v;
    const float* W = (z == 2) ? Wv : Wq;
    const float* bias = (z == 2) ? bv : bq;
    float* C = (z == 0) ? Qp : (z == 1) ? Kp : Vp;
    gemm_body(A, W, bias, C, 1);
}

__global__ __launch_bounds__(256, 2) void gemm_bias_kernel(
    const float* __restrict__ A, const float* __restrict__ W,
    const float* __restrict__ bias, float* __restrict__ C)
{
    gemm_body(A, W, bias, C, 0);
}

// ---------------------------------------------------------------------------
// Fused attention: per block = one (b,h) and 16 query rows, 512 threads.
// ---------------------------------------------------------------------------
#define SQ_OFF   (ROWS * SS_STRIDE)
#define SKV_OFF  (SQ_OFF + ROWS * 32)
#define SMEM_FLOATS (SKV_OFF + JC * 32)
#define SMEM_BYTES (SMEM_FLOATS * 4)

__global__ __launch_bounds__(THREADS, 2) void attn_kernel(
    const float* __restrict__ gammas, float* __restrict__ scores_out)
{
    extern __shared__ float smem[];
    float* sS   = smem;
    float* sQ   = smem + SQ_OFF;
    float* sKV  = smem + SKV_OFF;
    float* sRed = sKV;                           // reused after PV mainloop
    int tid = threadIdx.x;
    int lane = tid & 31, warp = tid >> 5;        // 16 warps
    int bh = blockIdx.y;
    int q0 = blockIdx.x * ROWS;
    int h = bh & (H_ - 1);
    int b = bh >> 3;
    const float* Q  = g_Qp + (size_t)bh * S_ * DH_;
    const float* Kp = g_Kp + (size_t)bh * S_ * DH_;
    const float* Vp = g_Vp + (size_t)bh * S_ * DH_;

    // ---- stage Q (scaled), swizzled: d4e = d4 ^ ((r>>1)&7) ----
    if (tid < ROWS * 8) {
        int r = tid >> 3, d4 = tid & 7;
        float4 qv = *(const float4*)&Q[(size_t)(q0 + r) * DH_ + d4 * 4];
        const float sc = 0.17677669529663688f;
        qv.x *= sc; qv.y *= sc; qv.z *= sc; qv.w *= sc;
        *(float4*)&sQ[r * 32 + ((d4 ^ ((r >> 1) & 7)) << 2)] = qv;
    }

    int nch = (q0 + ROWS + JC - 1) / JC;

    // QK tiling: thread -> 4 rows x 2 cols; 4 row-quarters x 128 col-pairs
    int rq = lane >> 3;                 // 0..3 -> rows rq*4..+3
    int r0 = rq * 4;
    int pp = warp * 8 + (lane & 7);     // col-pair index 0..127 (within chunk)
    int c0 = pp * 2;
    int ck = pp & 7;                    // k swizzle key for both cols of pair

    // ---- QK^T into sS ----
    for (int ch = 0; ch < nch; ch++) {
        int jb = ch * JC;
        __syncthreads();
        for (int f = tid; f < JC * 8; f += THREADS) {
            int j = f >> 3, d4 = f & 7;
            float4 kv = *(const float4*)&Kp[(size_t)(jb + j) * DH_ + d4 * 4];
            *(float4*)&sKV[j * 32 + ((d4 ^ ((j >> 1) & 7)) << 2)] = kv;
        }
        __syncthreads();
        float acc[4][2] = {};
        #pragma unroll
        for (int d4 = 0; d4 < 8; d4++) {
            float4 q4[4];
            #pragma unroll
            for (int r = 0; r < 4; r++) {
                int row = r0 + r;
                q4[r] = *(const float4*)&sQ[row * 32 + ((d4 ^ ((row >> 1) & 7)) << 2)];
            }
            int kswz = (d4 ^ ck) << 2;
            float4 ka = *(const float4*)&sKV[c0 * 32 + kswz];
            float4 kb = *(const float4*)&sKV[(c0 + 1) * 32 + kswz];
            #pragma unroll
            for (int r = 0; r < 4; r++) {
                acc[r][0] = fmaf(q4[r].x, ka.x, acc[r][0]);
                acc[r][0] = fmaf(q4[r].y, ka.y, acc[r][0]);
                acc[r][0] = fmaf(q4[r].z, ka.z, acc[r][0]);
                acc[r][0] = fmaf(q4[r].w, ka.w, acc[r][0]);
                acc[r][1] = fmaf(q4[r].x, kb.x, acc[r][1]);
                acc[r][1] = fmaf(q4[r].y, kb.y, acc[r][1]);
                acc[r][1] = fmaf(q4[r].z, kb.z, acc[r][1]);
                acc[r][1] = fmaf(q4[r].w, kb.w, acc[r][1]);
            }
        }
        #pragma unroll
        for (int r = 0; r < 4; r++)
            *(float2*)&sS[(size_t)(r0 + r) * SS_STRIDE + jb + c0] =
                make_float2(acc[r][0], acc[r][1]);
    }
    __syncthreads();

    // ---- row phase (1 row/warp), no max subtraction, 3 vectorized passes ----
    {
        float gam = -fabsf(gammas[h]);
        int qg = q0 + warp;
        int L = qg + 1;
        float* row = sS + (size_t)warp * SS_STRIDE;

        // Pass 1: Z1 = sum exp(s)
        float Z1 = 0.f;
        for (int j = lane * 4; j < L; j += 128) {
            float4 sv = *(const float4*)&row[j];
            if (j + 0 < L) Z1 += __expf(sv.x);
            if (j + 1 < L) Z1 += __expf(sv.y);
            if (j + 2 < L) Z1 += __expf(sv.z);
            if (j + 3 < L) Z1 += __expf(sv.w);
        }
        #pragma unroll
        for (int o = 16; o; o >>= 1) Z1 += __shfl_xor_sync(0xffffffffu, Z1, o);
        float invZ1 = __frcp_rn(Z1);

        // Pass 2: scan cum(exp), decay, p=exp(s*eff) unnormalized; Z2
        float running = 0.f, Z2 = 0.f;
        int nb = (L + 127) >> 7;
        for (int bi = 0; bi < nb; bi++) {
            int j = bi * 128 + lane * 4;
            float4 sv = *(const float4*)&row[j];
            float e0 = (j + 0 < L) ? __expf(sv.x) : 0.f;
            float e1 = (j + 1 < L) ? __expf(sv.y) : 0.f;
            float e2 = (j + 2 < L) ? __expf(sv.z) : 0.f;
            float e3 = (j + 3 < L) ? __expf(sv.w) : 0.f;
            float p1 = e0 + e1, p2 = p1 + e2, p3 = p2 + e3;
            float c = p3;
            #pragma unroll
            for (int o = 1; o < 32; o <<= 1) {
                float t = __shfl_up_sync(0xffffffffu, c, o);
                if (lane >= o) c += t;
            }
            float excl = running + c - p3;
            running += __shfl_sync(0xffffffffu, c, 31);
            float4 out = {0.f, 0.f, 0.f, 0.f};
            if (j + 0 < L) {
                float rem = 1.f - (excl + e0) * invZ1;
                float dist = sqrtf(fmaxf(rem * (float)(qg - j), 0.f));
                float eff = fmaxf(__expf(gam * dist), 1e-5f);
                out.x = __expf(sv.x * eff); Z2 += out.x;
            }
            if (j + 1 < L) {
                float rem = 1.f - (excl + p1) * invZ1;
                float dist = sqrtf(fmaxf(rem * (float)(qg - j - 1), 0.f));
                float eff = fmaxf(__expf(gam * dist), 1e-5f);
                out.y = __expf(sv.y * eff); Z2 += out.y;
            }
            if (j + 2 < L) {
                float rem = 1.f - (excl + p2) * invZ1;
                float dist = sqrtf(fmaxf(rem * (float)(qg - j - 2), 0.f));
                float eff = fmaxf(__expf(gam * dist), 1e-5f);
                out.z = __expf(sv.z * eff); Z2 += out.z;
            }
            if (j + 3 < L) {
                float rem = 1.f - (excl + p3) * invZ1;
                float dist = sqrtf(fmaxf(rem * (float)(qg - j - 3), 0.f));
                float eff = fmaxf(__expf(gam * dist), 1e-5f);
                out.w = __expf(sv.w * eff); Z2 += out.w;
            }
            *(float4*)&row[j] = out;
        }
        #pragma unroll
        for (int o = 16; o; o >>= 1) Z2 += __shfl_xor_sync(0xffffffffu, Z2, o);
        float invZ2 = __frcp_rn(Z2);

        // Pass 3: normalize, write row (for PV) + gmem scores (masked zeros)
        float* grow = scores_out + ((size_t)bh * S_ + qg) * S_;
        for (int j = lane * 4; j < S_; j += 128) {
            float4 pv = *(const float4*)&row[j];
            float4 p;
            p.x = (j + 0 < L) ? pv.x * invZ2 : 0.f;
            p.y = (j + 1 < L) ? pv.y * invZ2 : 0.f;
            p.z = (j + 2 < L) ? pv.z * invZ2 : 0.f;
            p.w = (j + 3 < L) ? pv.w * invZ2 : 0.f;
            *(float4*)&row[j] = p;
            __stcs((float4*)&grow[j], p);
        }
    }

    // ---- PV: L-split across 16 warps; thread holds ctx[16 rows], dim=lane ----
    float acc[ROWS];
    #pragma unroll
    for (int r = 0; r < ROWS; r++) acc[r] = 0.f;

    for (int ch = 0; ch < nch; ch++) {
        int jb = ch * JC;
        __syncthreads();
        for (int f = tid; f < JC * 8; f += THREADS) {
            int j = f >> 3, d4 = f & 7;
            *(float4*)&sKV[j * 32 + d4 * 4] =
                *(const float4*)&Vp[(size_t)(jb + j) * DH_ + d4 * 4];
        }
        __syncthreads();
        #pragma unroll
        for (int g = 0; g < 4; g++) {
            int jloc = warp * 16 + g * 4;
            int j = jb + jloc;
            float v0 = sKV[(jloc+0) * 32 + lane];
            float v1 = sKV[(jloc+1) * 32 + lane];
            float v2 = sKV[(jloc+2) * 32 + lane];
            float v3 = sKV[(jloc+3) * 32 + lane];
            #pragma unroll
            for (int r = 0; r < ROWS; r++) {
                float4 p4 = *(const float4*)&sS[(size_t)r * SS_STRIDE + j];
                float t = p4.x * v0 + p4.y * v1;
                t = fmaf(p4.z, v2, t);
                t = fmaf(p4.w, v3, t);
                acc[r] += t;
            }
        }
    }

    // ---- cross-warp reduction (16 -> 1) via reused sKV buffer ----
    #pragma unroll
    for (int step = 8; step >= 1; step >>= 1) {
        __syncthreads();
        if (warp >= step && warp < 2*step) {
            #pragma unroll
            for (int r = 0; r < ROWS; r++)
                sRed[(warp - step) * (ROWS*32) + r * 32 + lane] = acc[r];
        }
        __syncthreads();
        if (warp < step) {
            #pragma unroll
            for (int r = 0; r < ROWS; r++)
                acc[r] += sRed[warp * (ROWS*32) + r * 32 + lane];
        }
    }
    if (warp == 0) {
        #pragma unroll
        for (int r = 0; r < ROWS; r++)
            g_ctx[((size_t)(b * S_ + q0 + r)) * D_ + h * DH_ + lane] = acc[r];
    }
}

// ---------------------------------------------------------------------------
extern "C" void kernel_launch(void* const* d_in, const int* in_sizes, int n_in,
                              void* d_out, int out_size) {
    const float* q      = (const float*)d_in[0];
    const float* k      = (const float*)d_in[1];
    const float* v      = (const float*)d_in[2];
    const float* Wq     = (const float*)d_in[4];
    const float* bq     = (const float*)d_in[5];
    const float* Wv     = (const float*)d_in[6];
    const float* bv     = (const float*)d_in[7];
    const float* Wo     = (const float*)d_in[8];
    const float* bo     = (const float*)d_in[9];
    const float* gammas = (const float*)d_in[10];

    float* out    = (float*)d_out;                       // [B,S,D]
    float* scores = out + (size_t)B_ * S_ * D_;          // [B,H,S,S]

    float *Qp, *Kp, *Vp, *ctx;
    cudaGetSymbolAddress((void**)&Qp,  g_Qp);
    cudaGetSymbolAddress((void**)&Kp,  g_Kp);
    cudaGetSymbolAddress((void**)&Vp,  g_Vp);
    cudaGetSymbolAddress((void**)&ctx, g_ctx);

    proj3_kernel<<<dim3(2, 64, 3), 256>>>(q, k, v, Wq, bq, Wv, bv, Qp, Kp, Vp);

    cudaFuncSetAttribute(attn_kernel, cudaFuncAttributeMaxDynamicSharedMemorySize, SMEM_BYTES);
    attn_kernel<<<dim3(S_ / ROWS, BH_), THREADS, SMEM_BYTES>>>(gammas, scores);

    gemm_bias_kernel<<<dim3(2, 64), 256>>>(ctx, Wo, bo, out);
}

// round 7
// speedup vs baseline: 1.0265x; 1.0265x over previous
#include <cuda_runtime.h>
#include <math.h>

#define B_ 8
#define S_ 1024
#define D_ 256
#define H_ 8
#define DH_ 32
#define BH_ (B_*H_)
#define ROWS 16
#define JC 256
#define SS_STRIDE 1028
#define THREADS 512

// Scratch (device globals: no allocation allowed)
__device__ float g_Qp[BH_*S_*DH_];   // [B,H,S,DH]
__device__ float g_Kp[BH_*S_*DH_];
__device__ float g_Vp[BH_*S_*DH_];
__device__ float g_ctx[B_*S_*D_];    // attention output, [B,S,D]

// ---------------------------------------------------------------------------
// GEMM body: C[m,n] = sum_k A[m,k]*W[n,k] + bias[n]; 128x128 tile, 8x8 micro,
// double-buffered smem pipeline (1 sync per k-step, LDG hidden under FMA).
// ---------------------------------------------------------------------------
__device__ __forceinline__ void gemm_body(
    const float* __restrict__ A, const float* __restrict__ W,
    const float* __restrict__ bias, float* __restrict__ C, int headLayout)
{
    __shared__ float sA[2][16][132];
    __shared__ float sW[2][16][132];
    const int K = D_;
    int tid = threadIdx.x;
    int tx = tid & 15, ty = tid >> 4;            // 16x16 thread grid
    int m0 = blockIdx.y * 128, n0 = blockIdx.x * 128;
    int lr = tid >> 2, lc = (tid & 3) * 4;       // staging: rows lr, lr+64
    float acc[8][8] = {};

    // Preload k0 = 0 into buffer 0
    {
        float4 a0 = *(const float4*)&A[(size_t)(m0 + lr) * K + lc];
        float4 a1 = *(const float4*)&A[(size_t)(m0 + lr + 64) * K + lc];
        float4 w0 = *(const float4*)&W[(size_t)(n0 + lr) * K + lc];
        float4 w1 = *(const float4*)&W[(size_t)(n0 + lr + 64) * K + lc];
        sA[0][lc+0][lr] = a0.x; sA[0][lc+1][lr] = a0.y; sA[0][lc+2][lr] = a0.z; sA[0][lc+3][lr] = a0.w;
        sA[0][lc+0][lr+64] = a1.x; sA[0][lc+1][lr+64] = a1.y; sA[0][lc+2][lr+64] = a1.z; sA[0][lc+3][lr+64] = a1.w;
        sW[0][lc+0][lr] = w0.x; sW[0][lc+1][lr] = w0.y; sW[0][lc+2][lr] = w0.z; sW[0][lc+3][lr] = w0.w;
        sW[0][lc+0][lr+64] = w1.x; sW[0][lc+1][lr+64] = w1.y; sW[0][lc+2][lr+64] = w1.z; sW[0][lc+3][lr+64] = w1.w;
    }
    __syncthreads();

    for (int k0 = 0; k0 < K; k0 += 16) {
        int buf = (k0 >> 4) & 1;
        int nxt = buf ^ 1;
        float4 na0, na1, nw0, nw1;
        bool more = (k0 + 16) < K;
        if (more) {   // issue next-tile LDGs early; latency hidden by FMAs
            int kn = k0 + 16;
            na0 = *(const float4*)&A[(size_t)(m0 + lr) * K + kn + lc];
            na1 = *(const float4*)&A[(size_t)(m0 + lr + 64) * K + kn + lc];
            nw0 = *(const float4*)&W[(size_t)(n0 + lr) * K + kn + lc];
            nw1 = *(const float4*)&W[(size_t)(n0 + lr + 64) * K + kn + lc];
        }
        #pragma unroll
        for (int kk = 0; kk < 16; kk++) {
            float4 alo = *(const float4*)&sA[buf][kk][ty*8];
            float4 ahi = *(const float4*)&sA[buf][kk][ty*8+4];
            float4 blo = *(const float4*)&sW[buf][kk][tx*8];
            float4 bhi = *(const float4*)&sW[buf][kk][tx*8+4];
            float a[8] = {alo.x, alo.y, alo.z, alo.w, ahi.x, ahi.y, ahi.z, ahi.w};
            float bb[8] = {blo.x, blo.y, blo.z, blo.w, bhi.x, bhi.y, bhi.z, bhi.w};
            #pragma unroll
            for (int i = 0; i < 8; i++)
                #pragma unroll
                for (int j = 0; j < 8; j++)
                    acc[i][j] = fmaf(a[i], bb[j], acc[i][j]);
        }
        if (more) {
            sA[nxt][lc+0][lr] = na0.x; sA[nxt][lc+1][lr] = na0.y; sA[nxt][lc+2][lr] = na0.z; sA[nxt][lc+3][lr] = na0.w;
            sA[nxt][lc+0][lr+64] = na1.x; sA[nxt][lc+1][lr+64] = na1.y; sA[nxt][lc+2][lr+64] = na1.z; sA[nxt][lc+3][lr+64] = na1.w;
            sW[nxt][lc+0][lr] = nw0.x; sW[nxt][lc+1][lr] = nw0.y; sW[nxt][lc+2][lr] = nw0.z; sW[nxt][lc+3][lr] = nw0.w;
            sW[nxt][lc+0][lr+64] = nw1.x; sW[nxt][lc+1][lr+64] = nw1.y; sW[nxt][lc+2][lr+64] = nw1.z; sW[nxt][lc+3][lr+64] = nw1.w;
        }
        __syncthreads();
    }
    #pragma unroll
    for (int i = 0; i < 8; i++) {
        int m = m0 + ty*8 + i;
        int bbat = m >> 10, ss = m & 1023;
        #pragma unroll
        for (int j = 0; j < 8; j++) {
            int n = n0 + tx*8 + j;
            float val = acc[i][j] + bias[n];
            if (headLayout) {
                int h = n >> 5, dh = n & 31;
                C[(((size_t)(bbat*H_ + h) * S_) + ss) * DH_ + dh] = val;
            } else {
                C[(size_t)m * D_ + n] = val;
            }
        }
    }
}

// 3 projection GEMMs in one launch (z selects)
__global__ __launch_bounds__(256, 2) void proj3_kernel(
    const float* __restrict__ q, const float* __restrict__ k, const float* __restrict__ v,
    const float* __restrict__ Wq, const float* __restrict__ bq,
    const float* __restrict__ Wv, const float* __restrict__ bv,
    float* __restrict__ Qp, float* __restrict__ Kp, float* __restrict__ Vp)
{
    int z = blockIdx.z;
    const float* A = (z == 0) ? q : (z == 1) ? k : v;
    const float* W = (z == 2) ? Wv : Wq;
    const float* bias = (z == 2) ? bv : bq;
    float* C = (z == 0) ? Qp : (z == 1) ? Kp : Vp;
    gemm_body(A, W, bias, C, 1);
}

__global__ __launch_bounds__(256, 2) void gemm_bias_kernel(
    const float* __restrict__ A, const float* __restrict__ W,
    const float* __restrict__ bias, float* __restrict__ C)
{
    gemm_body(A, W, bias, C, 0);
}

// ---------------------------------------------------------------------------
// Fused attention: per block = one (b,h) and 16 query rows, 512 threads.
// ---------------------------------------------------------------------------
#define SQ_OFF   (ROWS * SS_STRIDE)
#define SKV_OFF  (SQ_OFF + ROWS * 32)
#define SMEM_FLOATS (SKV_OFF + JC * 32)
#define SMEM_BYTES (SMEM_FLOATS * 4)

__global__ __launch_bounds__(THREADS, 2) void attn_kernel(
    const float* __restrict__ gammas, float* __restrict__ scores_out)
{
    extern __shared__ float smem[];
    float* sS   = smem;
    float* sQ   = smem + SQ_OFF;
    float* sKV  = smem + SKV_OFF;
    float* sRed = sKV;                           // reused after PV mainloop
    int tid = threadIdx.x;
    int lane = tid & 31, warp = tid >> 5;        // 16 warps
    int bh = blockIdx.y;
    int q0 = blockIdx.x * ROWS;
    int h = bh & (H_ - 1);
    int b = bh >> 3;
    const float* Q  = g_Qp + (size_t)bh * S_ * DH_;
    const float* Kp = g_Kp + (size_t)bh * S_ * DH_;
    const float* Vp = g_Vp + (size_t)bh * S_ * DH_;

    // ---- stage Q (scaled), swizzled: d4e = d4 ^ ((r>>1)&7) ----
    if (tid < ROWS * 8) {
        int r = tid >> 3, d4 = tid & 7;
        float4 qv = *(const float4*)&Q[(size_t)(q0 + r) * DH_ + d4 * 4];
        const float sc = 0.17677669529663688f;
        qv.x *= sc; qv.y *= sc; qv.z *= sc; qv.w *= sc;
        *(float4*)&sQ[r * 32 + ((d4 ^ ((r >> 1) & 7)) << 2)] = qv;
    }

    int nch = (q0 + ROWS + JC - 1) / JC;

    // QK tiling: thread -> 4 rows x 2 cols; 4 row-quarters x 128 col-pairs
    int rq = lane >> 3;
    int r0 = rq * 4;
    int pp = warp * 8 + (lane & 7);     // col-pair index 0..127 (within chunk)
    int c0 = pp * 2;
    int ck = pp & 7;

    // ---- QK^T into sS ----
    for (int ch = 0; ch < nch; ch++) {
        int jb = ch * JC;
        __syncthreads();
        for (int f = tid; f < JC * 8; f += THREADS) {
            int j = f >> 3, d4 = f & 7;
            float4 kv = *(const float4*)&Kp[(size_t)(jb + j) * DH_ + d4 * 4];
            *(float4*)&sKV[j * 32 + ((d4 ^ ((j >> 1) & 7)) << 2)] = kv;
        }
        __syncthreads();
        float acc[4][2] = {};
        #pragma unroll
        for (int d4 = 0; d4 < 8; d4++) {
            float4 q4[4];
            #pragma unroll
            for (int r = 0; r < 4; r++) {
                int row = r0 + r;
                q4[r] = *(const float4*)&sQ[row * 32 + ((d4 ^ ((row >> 1) & 7)) << 2)];
            }
            int kswz = (d4 ^ ck) << 2;
            float4 ka = *(const float4*)&sKV[c0 * 32 + kswz];
            float4 kb = *(const float4*)&sKV[(c0 + 1) * 32 + kswz];
            #pragma unroll
            for (int r = 0; r < 4; r++) {
                acc[r][0] = fmaf(q4[r].x, ka.x, acc[r][0]);
                acc[r][0] = fmaf(q4[r].y, ka.y, acc[r][0]);
                acc[r][0] = fmaf(q4[r].z, ka.z, acc[r][0]);
                acc[r][0] = fmaf(q4[r].w, ka.w, acc[r][0]);
                acc[r][1] = fmaf(q4[r].x, kb.x, acc[r][1]);
                acc[r][1] = fmaf(q4[r].y, kb.y, acc[r][1]);
                acc[r][1] = fmaf(q4[r].z, kb.z, acc[r][1]);
                acc[r][1] = fmaf(q4[r].w, kb.w, acc[r][1]);
            }
        }
        #pragma unroll
        for (int r = 0; r < 4; r++)
            *(float2*)&sS[(size_t)(r0 + r) * SS_STRIDE + jb + c0] =
                make_float2(acc[r][0], acc[r][1]);
    }
    __syncthreads();

    // ---- row phase (1 row/warp), no max subtraction, 3 vectorized passes ----
    {
        float gam = -fabsf(gammas[h]);
        int qg = q0 + warp;
        int L = qg + 1;
        float* row = sS + (size_t)warp * SS_STRIDE;

        // Pass 1: Z1 = sum exp(s)
        float Z1 = 0.f;
        for (int j = lane * 4; j < L; j += 128) {
            float4 sv = *(const float4*)&row[j];
            if (j + 0 < L) Z1 += __expf(sv.x);
            if (j + 1 < L) Z1 += __expf(sv.y);
            if (j + 2 < L) Z1 += __expf(sv.z);
            if (j + 3 < L) Z1 += __expf(sv.w);
        }
        #pragma unroll
        for (int o = 16; o; o >>= 1) Z1 += __shfl_xor_sync(0xffffffffu, Z1, o);
        float invZ1 = __frcp_rn(Z1);

        // Pass 2: scan cum(exp), decay, p=exp(s*eff) unnormalized; Z2
        float running = 0.f, Z2 = 0.f;
        int nb = (L + 127) >> 7;
        for (int bi = 0; bi < nb; bi++) {
            int j = bi * 128 + lane * 4;
            float4 sv = *(const float4*)&row[j];
            float e0 = (j + 0 < L) ? __expf(sv.x) : 0.f;
            float e1 = (j + 1 < L) ? __expf(sv.y) : 0.f;
            float e2 = (j + 2 < L) ? __expf(sv.z) : 0.f;
            float e3 = (j + 3 < L) ? __expf(sv.w) : 0.f;
            float p1 = e0 + e1, p2 = p1 + e2, p3 = p2 + e3;
            float c = p3;
            #pragma unroll
            for (int o = 1; o < 32; o <<= 1) {
                float t = __shfl_up_sync(0xffffffffu, c, o);
                if (lane >= o) c += t;
            }
            float excl = running + c - p3;
            running += __shfl_sync(0xffffffffu, c, 31);
            float4 out = {0.f, 0.f, 0.f, 0.f};
            if (j + 0 < L) {
                float rem = 1.f - (excl + e0) * invZ1;
                float dist = sqrtf(fmaxf(rem * (float)(qg - j), 0.f));
                float eff = fmaxf(__expf(gam * dist), 1e-5f);
                out.x = __expf(sv.x * eff); Z2 += out.x;
            }
            if (j + 1 < L) {
                float rem = 1.f - (excl + p1) * invZ1;
                float dist = sqrtf(fmaxf(rem * (float)(qg - j - 1), 0.f));
                float eff = fmaxf(__expf(gam * dist), 1e-5f);
                out.y = __expf(sv.y * eff); Z2 += out.y;
            }
            if (j + 2 < L) {
                float rem = 1.f - (excl + p2) * invZ1;
                float dist = sqrtf(fmaxf(rem * (float)(qg - j - 2), 0.f));
                float eff = fmaxf(__expf(gam * dist), 1e-5f);
                out.z = __expf(sv.z * eff); Z2 += out.z;
            }
            if (j + 3 < L) {
                float rem = 1.f - (excl + p3) * invZ1;
                float dist = sqrtf(fmaxf(rem * (float)(qg - j - 3), 0.f));
                float eff = fmaxf(__expf(gam * dist), 1e-5f);
                out.w = __expf(sv.w * eff); Z2 += out.w;
            }
            *(float4*)&row[j] = out;
        }
        #pragma unroll
        for (int o = 16; o; o >>= 1) Z2 += __shfl_xor_sync(0xffffffffu, Z2, o);
        float invZ2 = __frcp_rn(Z2);

        // Pass 3: normalize, write row (for PV) + gmem scores (masked zeros)
        float* grow = scores_out + ((size_t)bh * S_ + qg) * S_;
        for (int j = lane * 4; j < S_; j += 128) {
            float4 pv = *(const float4*)&row[j];
            float4 p;
            p.x = (j + 0 < L) ? pv.x * invZ2 : 0.f;
            p.y = (j + 1 < L) ? pv.y * invZ2 : 0.f;
            p.z = (j + 2 < L) ? pv.z * invZ2 : 0.f;
            p.w = (j + 3 < L) ? pv.w * invZ2 : 0.f;
            *(float4*)&row[j] = p;
            __stcs((float4*)&grow[j], p);
        }
    }

    // ---- PV: L-split across 16 warps; thread holds ctx[16 rows], dim=lane ----
    float acc[ROWS];
    #pragma unroll
    for (int r = 0; r < ROWS; r++) acc[r] = 0.f;

    for (int ch = 0; ch < nch; ch++) {
        int jb = ch * JC;
        __syncthreads();
        for (int f = tid; f < JC * 8; f += THREADS) {
            int j = f >> 3, d4 = f & 7;
            *(float4*)&sKV[j * 32 + d4 * 4] =
                *(const float4*)&Vp[(size_t)(jb + j) * DH_ + d4 * 4];
        }
        __syncthreads();
        #pragma unroll
        for (int g = 0; g < 4; g++) {
            int jloc = warp * 16 + g * 4;
            int j = jb + jloc;
            float v0 = sKV[(jloc+0) * 32 + lane];
            float v1 = sKV[(jloc+1) * 32 + lane];
            float v2 = sKV[(jloc+2) * 32 + lane];
            float v3 = sKV[(jloc+3) * 32 + lane];
            #pragma unroll
            for (int r = 0; r < ROWS; r++) {
                float4 p4 = *(const float4*)&sS[(size_t)r * SS_STRIDE + j];
                float t = p4.x * v0 + p4.y * v1;
                t = fmaf(p4.z, v2, t);
                t = fmaf(p4.w, v3, t);
                acc[r] += t;
            }
        }
    }

    // ---- cross-warp reduction (16 -> 1) via reused sKV buffer ----
    #pragma unroll
    for (int step = 8; step >= 1; step >>= 1) {
        __syncthreads();
        if (warp >= step && warp < 2*step) {
            #pragma unroll
            for (int r = 0; r < ROWS; r++)
                sRed[(warp - step) * (ROWS*32) + r * 32 + lane] = acc[r];
        }
        __syncthreads();
        if (warp < step) {
            #pragma unroll
            for (int r = 0; r < ROWS; r++)
                acc[r] += sRed[warp * (ROWS*32) + r * 32 + lane];
        }
    }
    if (warp == 0) {
        #pragma unroll
        for (int r = 0; r < ROWS; r++)
            g_ctx[((size_t)(b * S_ + q0 + r)) * D_ + h * DH_ + lane] = acc[r];
    }
}

// ---------------------------------------------------------------------------
extern "C" void kernel_launch(void* const* d_in, const int* in_sizes, int n_in,
                              void* d_out, int out_size) {
    const float* q      = (const float*)d_in[0];
    const float* k      = (const float*)d_in[1];
    const float* v      = (const float*)d_in[2];
    const float* Wq     = (const float*)d_in[4];
    const float* bq     = (const float*)d_in[5];
    const float* Wv     = (const float*)d_in[6];
    const float* bv     = (const float*)d_in[7];
    const float* Wo     = (const float*)d_in[8];
    const float* bo     = (const float*)d_in[9];
    const float* gammas = (const float*)d_in[10];

    float* out    = (float*)d_out;                       // [B,S,D]
    float* scores = out + (size_t)B_ * S_ * D_;          // [B,H,S,S]

    float *Qp, *Kp, *Vp, *ctx;
    cudaGetSymbolAddress((void**)&Qp,  g_Qp);
    cudaGetSymbolAddress((void**)&Kp,  g_Kp);
    cudaGetSymbolAddress((void**)&Vp,  g_Vp);
    cudaGetSymbolAddress((void**)&ctx, g_ctx);

    proj3_kernel<<<dim3(2, 64, 3), 256>>>(q, k, v, Wq, bq, Wv, bv, Qp, Kp, Vp);

    cudaFuncSetAttribute(attn_kernel, cudaFuncAttributeMaxDynamicSharedMemorySize, SMEM_BYTES);
    attn_kernel<<<dim3(S_ / ROWS, BH_), THREADS, SMEM_BYTES>>>(gammas, scores);

    gemm_bias_kernel<<<dim3(2, 64), 256>>>(ctx, Wo, bo, out);
}

// round 9
// speedup vs baseline: 1.1595x; 1.1296x over previous
#include <cuda_runtime.h>
#include <cuda_bf16.h>
#include <mma.h>
#include <math.h>
#include <cstdint>

using namespace nvcuda;

#define B_ 8
#define S_ 1024
#define D_ 256
#define H_ 8
#define DH_ 32
#define BH_ (B_*H_)
#define ROWS 16
#define JC 256
#define SS_STRIDE 1028
#define THREADS 512
#define GT 256
#define KC 32
#define LDA 40
#define LDC 132
#define GS_TOTAL (128 * LDC * 4)   // fp32 C tile; operand staging aliases (smaller)

// Scratch (device globals: no allocation allowed)
__device__ float g_Qp[BH_*S_*DH_];   // [B,H,S,DH]
__device__ float g_Kp[BH_*S_*DH_];
__device__ float g_Vp[BH_*S_*DH_];
__device__ float g_ctx[B_*S_*D_];    // attention output, [B,S,D]

// ---------------------------------------------------------------------------
// Tensor-core GEMM (wmma bf16 split 3-term): C = A @ W^T + bias
// A [M,256] fp32, W [N,256] fp32; M=8192, N=256. 128x128 tile/CTA, 8 warps.
// ---------------------------------------------------------------------------
__device__ __forceinline__ void gemm_tc_body(
    const float* __restrict__ A, const float* __restrict__ W,
    const float* __restrict__ bias, float* __restrict__ C, int headLayout)
{
    extern __shared__ char gsm[];
    __nv_bfloat16* sAhi = (__nv_bfloat16*)gsm;          // [128][LDA]
    __nv_bfloat16* sAlo = sAhi + 128 * LDA;
    __nv_bfloat16* sBhi = sAlo + 128 * LDA;
    __nv_bfloat16* sBlo = sBhi + 128 * LDA;
    float* sC = (float*)gsm;                             // reused after mainloop

    int tid = threadIdx.x;
    int warp = tid >> 5;
    int m0 = blockIdx.y * 128, n0 = blockIdx.x * 128;
    int mw = (warp >> 2) * 64;        // warp row base (0 or 64)
    int nw = (warp & 3) * 32;         // warp col base (0,32,64,96)

    wmma::fragment<wmma::accumulator, 16, 16, 16, float> acc[4][2];
    #pragma unroll
    for (int i = 0; i < 4; i++)
        #pragma unroll
        for (int j = 0; j < 2; j++)
            wmma::fill_fragment(acc[i][j], 0.0f);

    for (int kc = 0; kc < D_; kc += KC) {
        __syncthreads();   // previous chunk fully consumed
        // stage A chunk [128 x 32] fp32 -> bf16 hi/lo
        #pragma unroll
        for (int it = 0; it < 4; it++) {
            int idx = tid + it * GT;          // 1024 float4
            int r = idx >> 3, c4 = (idx & 7) << 2;
            float4 x = *(const float4*)&A[(size_t)(m0 + r) * D_ + kc + c4];
            __nv_bfloat16 hx = __float2bfloat16_rn(x.x);
            __nv_bfloat16 hy = __float2bfloat16_rn(x.y);
            __nv_bfloat16 hz = __float2bfloat16_rn(x.z);
            __nv_bfloat16 hw = __float2bfloat16_rn(x.w);
            *(__nv_bfloat162*)&sAhi[r*LDA + c4]     = __nv_bfloat162(hx, hy);
            *(__nv_bfloat162*)&sAhi[r*LDA + c4 + 2] = __nv_bfloat162(hz, hw);
            *(__nv_bfloat162*)&sAlo[r*LDA + c4] = __nv_bfloat162(
                __float2bfloat16_rn(x.x - __bfloat162float(hx)),
                __float2bfloat16_rn(x.y - __bfloat162float(hy)));
            *(__nv_bfloat162*)&sAlo[r*LDA + c4 + 2] = __nv_bfloat162(
                __float2bfloat16_rn(x.z - __bfloat162float(hz)),
                __float2bfloat16_rn(x.w - __bfloat162float(hw)));
        }
        // stage B chunk = W[n0..n0+127][kc..kc+31]
        #pragma unroll
        for (int it = 0; it < 4; it++) {
            int idx = tid + it * GT;
            int r = idx >> 3, c4 = (idx & 7) << 2;
            float4 x = *(const float4*)&W[(size_t)(n0 + r) * D_ + kc + c4];
            __nv_bfloat16 hx = __float2bfloat16_rn(x.x);
            __nv_bfloat16 hy = __float2bfloat16_rn(x.y);
            __nv_bfloat16 hz = __float2bfloat16_rn(x.z);
            __nv_bfloat16 hw = __float2bfloat16_rn(x.w);
            *(__nv_bfloat162*)&sBhi[r*LDA + c4]     = __nv_bfloat162(hx, hy);
            *(__nv_bfloat162*)&sBhi[r*LDA + c4 + 2] = __nv_bfloat162(hz, hw);
            *(__nv_bfloat162*)&sBlo[r*LDA + c4] = __nv_bfloat162(
                __float2bfloat16_rn(x.x - __bfloat162float(hx)),
                __float2bfloat16_rn(x.y - __bfloat162float(hy)));
            *(__nv_bfloat162*)&sBlo[r*LDA + c4 + 2] = __nv_bfloat162(
                __float2bfloat16_rn(x.z - __bfloat162float(hz)),
                __float2bfloat16_rn(x.w - __bfloat162float(hw)));
        }
        __syncthreads();

        #pragma unroll
        for (int kk = 0; kk < KC; kk += 16) {
            wmma::fragment<wmma::matrix_a, 16, 16, 16, __nv_bfloat16, wmma::row_major> ah[4], al[4];
            wmma::fragment<wmma::matrix_b, 16, 16, 16, __nv_bfloat16, wmma::col_major> bh[2], bl[2];
            #pragma unroll
            for (int i = 0; i < 4; i++) {
                wmma::load_matrix_sync(ah[i], &sAhi[(mw + i*16) * LDA + kk], LDA);
                wmma::load_matrix_sync(al[i], &sAlo[(mw + i*16) * LDA + kk], LDA);
            }
            #pragma unroll
            for (int j = 0; j < 2; j++) {
                wmma::load_matrix_sync(bh[j], &sBhi[(nw + j*16) * LDA + kk], LDA);
                wmma::load_matrix_sync(bl[j], &sBlo[(nw + j*16) * LDA + kk], LDA);
            }
            #pragma unroll
            for (int i = 0; i < 4; i++)
                #pragma unroll
                for (int j = 0; j < 2; j++) {
                    wmma::mma_sync(acc[i][j], ah[i], bh[j], acc[i][j]);
                    wmma::mma_sync(acc[i][j], ah[i], bl[j], acc[i][j]);
                    wmma::mma_sync(acc[i][j], al[i], bh[j], acc[i][j]);
                }
        }
    }
    __syncthreads();   // done reading operands; reuse smem as C tile

    #pragma unroll
    for (int i = 0; i < 4; i++)
        #pragma unroll
        for (int j = 0; j < 2; j++)
            wmma::store_matrix_sync(&sC[(mw + i*16) * LDC + nw + j*16],
                                    acc[i][j], LDC, wmma::mem_row_major);
    __syncthreads();

    // epilogue: bias add + scatter
    #pragma unroll
    for (int it = 0; it < 16; it++) {
        int idx = tid + it * GT;          // 4096 float4
        int r = idx >> 5, c4 = (idx & 31) << 2;
        float4 v = *(const float4*)&sC[r * LDC + c4];
        int n = n0 + c4;
        v.x += bias[n]; v.y += bias[n+1]; v.z += bias[n+2]; v.w += bias[n+3];
        int m = m0 + r, bbat = m >> 10, ss = m & 1023;
        if (headLayout) {
            int h = n >> 5, dh = n & 31;
            *(float4*)&C[(((size_t)(bbat * H_ + h)) * S_ + ss) * DH_ + dh] = v;
        } else {
            *(float4*)&C[(size_t)m * D_ + n] = v;
        }
    }
}

__global__ __launch_bounds__(GT) void proj3_kernel(
    const float* __restrict__ q, const float* __restrict__ k, const float* __restrict__ v,
    const float* __restrict__ Wq, const float* __restrict__ bq,
    const float* __restrict__ Wv, const float* __restrict__ bv,
    float* __restrict__ Qp, float* __restrict__ Kp, float* __restrict__ Vp)
{
    int z = blockIdx.z;
    const float* A = (z == 0) ? q : (z == 1) ? k : v;
    const float* W = (z == 2) ? Wv : Wq;
    const float* bias = (z == 2) ? bv : bq;
    float* C = (z == 0) ? Qp : (z == 1) ? Kp : Vp;
    gemm_tc_body(A, W, bias, C, 1);
}

__global__ __launch_bounds__(GT) void gemm_bias_kernel(
    const float* __restrict__ A, const float* __restrict__ W,
    const float* __restrict__ bias, float* __restrict__ C)
{
    gemm_tc_body(A, W, bias, C, 0);
}

// ---------------------------------------------------------------------------
// Fused attention: per block = one (b,h) and 16 query rows, 512 threads.
// (unchanged from round 7 passing version)
// ---------------------------------------------------------------------------
#define SQ_OFF   (ROWS * SS_STRIDE)
#define SKV_OFF  (SQ_OFF + ROWS * 32)
#define SMEM_FLOATS (SKV_OFF + JC * 32)
#define SMEM_BYTES (SMEM_FLOATS * 4)

__global__ __launch_bounds__(THREADS, 2) void attn_kernel(
    const float* __restrict__ gammas, float* __restrict__ scores_out)
{
    extern __shared__ float smem[];
    float* sS   = smem;
    float* sQ   = smem + SQ_OFF;
    float* sKV  = smem + SKV_OFF;
    float* sRed = sKV;
    int tid = threadIdx.x;
    int lane = tid & 31, warp = tid >> 5;
    int bh = blockIdx.y;
    int q0 = blockIdx.x * ROWS;
    int h = bh & (H_ - 1);
    int b = bh >> 3;
    const float* Q  = g_Qp + (size_t)bh * S_ * DH_;
    const float* Kp = g_Kp + (size_t)bh * S_ * DH_;
    const float* Vp = g_Vp + (size_t)bh * S_ * DH_;

    if (tid < ROWS * 8) {
        int r = tid >> 3, d4 = tid & 7;
        float4 qv = *(const float4*)&Q[(size_t)(q0 + r) * DH_ + d4 * 4];
        const float sc = 0.17677669529663688f;
        qv.x *= sc; qv.y *= sc; qv.z *= sc; qv.w *= sc;
        *(float4*)&sQ[r * 32 + ((d4 ^ ((r >> 1) & 7)) << 2)] = qv;
    }

    int nch = (q0 + ROWS + JC - 1) / JC;

    int rq = lane >> 3;
    int r0 = rq * 4;
    int pp = warp * 8 + (lane & 7);
    int c0 = pp * 2;
    int ck = pp & 7;

    for (int ch = 0; ch < nch; ch++) {
        int jb = ch * JC;
        __syncthreads();
        for (int f = tid; f < JC * 8; f += THREADS) {
            int j = f >> 3, d4 = f & 7;
            float4 kv = *(const float4*)&Kp[(size_t)(jb + j) * DH_ + d4 * 4];
            *(float4*)&sKV[j * 32 + ((d4 ^ ((j >> 1) & 7)) << 2)] = kv;
        }
        __syncthreads();
        float acc[4][2] = {};
        #pragma unroll
        for (int d4 = 0; d4 < 8; d4++) {
            float4 q4[4];
            #pragma unroll
            for (int r = 0; r < 4; r++) {
                int row = r0 + r;
                q4[r] = *(const float4*)&sQ[row * 32 + ((d4 ^ ((row >> 1) & 7)) << 2)];
            }
            int kswz = (d4 ^ ck) << 2;
            float4 ka = *(const float4*)&sKV[c0 * 32 + kswz];
            float4 kb = *(const float4*)&sKV[(c0 + 1) * 32 + kswz];
            #pragma unroll
            for (int r = 0; r < 4; r++) {
                acc[r][0] = fmaf(q4[r].x, ka.x, acc[r][0]);
                acc[r][0] = fmaf(q4[r].y, ka.y, acc[r][0]);
                acc[r][0] = fmaf(q4[r].z, ka.z, acc[r][0]);
                acc[r][0] = fmaf(q4[r].w, ka.w, acc[r][0]);
                acc[r][1] = fmaf(q4[r].x, kb.x, acc[r][1]);
                acc[r][1] = fmaf(q4[r].y, kb.y, acc[r][1]);
                acc[r][1] = fmaf(q4[r].z, kb.z, acc[r][1]);
                acc[r][1] = fmaf(q4[r].w, kb.w, acc[r][1]);
            }
        }
        #pragma unroll
        for (int r = 0; r < 4; r++)
            *(float2*)&sS[(size_t)(r0 + r) * SS_STRIDE + jb + c0] =
                make_float2(acc[r][0], acc[r][1]);
    }
    __syncthreads();

    {
        float gam = -fabsf(gammas[h]);
        int qg = q0 + warp;
        int L = qg + 1;
        float* row = sS + (size_t)warp * SS_STRIDE;

        float Z1 = 0.f;
        for (int j = lane * 4; j < L; j += 128) {
            float4 sv = *(const float4*)&row[j];
            if (j + 0 < L) Z1 += __expf(sv.x);
            if (j + 1 < L) Z1 += __expf(sv.y);
            if (j + 2 < L) Z1 += __expf(sv.z);
            if (j + 3 < L) Z1 += __expf(sv.w);
        }
        #pragma unroll
        for (int o = 16; o; o >>= 1) Z1 += __shfl_xor_sync(0xffffffffu, Z1, o);
        float invZ1 = __frcp_rn(Z1);

        float running = 0.f, Z2 = 0.f;
        int nb = (L + 127) >> 7;
        for (int bi = 0; bi < nb; bi++) {
            int j = bi * 128 + lane * 4;
            float4 sv = *(const float4*)&row[j];
            float e0 = (j + 0 < L) ? __expf(sv.x) : 0.f;
            float e1 = (j + 1 < L) ? __expf(sv.y) : 0.f;
            float e2 = (j + 2 < L) ? __expf(sv.z) : 0.f;
            float e3 = (j + 3 < L) ? __expf(sv.w) : 0.f;
            float p1 = e0 + e1, p2 = p1 + e2, p3 = p2 + e3;
            float c = p3;
            #pragma unroll
            for (int o = 1; o < 32; o <<= 1) {
                float t = __shfl_up_sync(0xffffffffu, c, o);
                if (lane >= o) c += t;
            }
            float excl = running + c - p3;
            running += __shfl_sync(0xffffffffu, c, 31);
            float4 out = {0.f, 0.f, 0.f, 0.f};
            if (j + 0 < L) {
                float rem = 1.f - (excl + e0) * invZ1;
                float dist = sqrtf(fmaxf(rem * (float)(qg - j), 0.f));
                float eff = fmaxf(__expf(gam * dist), 1e-5f);
                out.x = __expf(sv.x * eff); Z2 += out.x;
            }
            if (j + 1 < L) {
                float rem = 1.f - (excl + p1) * invZ1;
                float dist = sqrtf(fmaxf(rem * (float)(qg - j - 1), 0.f));
                float eff = fmaxf(__expf(gam * dist), 1e-5f);
                out.y = __expf(sv.y * eff); Z2 += out.y;
            }
            if (j + 2 < L) {
                float rem = 1.f - (excl + p2) * invZ1;
                float dist = sqrtf(fmaxf(rem * (float)(qg - j - 2), 0.f));
                float eff = fmaxf(__expf(gam * dist), 1e-5f);
                out.z = __expf(sv.z * eff); Z2 += out.z;
            }
            if (j + 3 < L) {
                float rem = 1.f - (excl + p3) * invZ1;
                float dist = sqrtf(fmaxf(rem * (float)(qg - j - 3), 0.f));
                float eff = fmaxf(__expf(gam * dist), 1e-5f);
                out.w = __expf(sv.w * eff); Z2 += out.w;
            }
            *(float4*)&row[j] = out;
        }
        #pragma unroll
        for (int o = 16; o; o >>= 1) Z2 += __shfl_xor_sync(0xffffffffu, Z2, o);
        float invZ2 = __frcp_rn(Z2);

        float* grow = scores_out + ((size_t)bh * S_ + qg) * S_;
        for (int j = lane * 4; j < S_; j += 128) {
            float4 pv = *(const float4*)&row[j];
            float4 p;
            p.x = (j + 0 < L) ? pv.x * invZ2 : 0.f;
            p.y = (j + 1 < L) ? pv.y * invZ2 : 0.f;
            p.z = (j + 2 < L) ? pv.z * invZ2 : 0.f;
            p.w = (j + 3 < L) ? pv.w * invZ2 : 0.f;
            *(float4*)&row[j] = p;
            __stcs((float4*)&grow[j], p);
        }
    }

    float acc[ROWS];
    #pragma unroll
    for (int r = 0; r < ROWS; r++) acc[r] = 0.f;

    for (int ch = 0; ch < nch; ch++) {
        int jb = ch * JC;
        __syncthreads();
        for (int f = tid; f < JC * 8; f += THREADS) {
            int j = f >> 3, d4 = f & 7;
            *(float4*)&sKV[j * 32 + d4 * 4] =
                *(const float4*)&Vp[(size_t)(jb + j) * DH_ + d4 * 4];
        }
        __syncthreads();
        #pragma unroll
        for (int g = 0; g < 4; g++) {
            int jloc = warp * 16 + g * 4;
            int j = jb + jloc;
            float v0 = sKV[(jloc+0) * 32 + lane];
            float v1 = sKV[(jloc+1) * 32 + lane];
            float v2 = sKV[(jloc+2) * 32 + lane];
            float v3 = sKV[(jloc+3) * 32 + lane];
            #pragma unroll
            for (int r = 0; r < ROWS; r++) {
                float4 p4 = *(const float4*)&sS[(size_t)r * SS_STRIDE + j];
                float t = p4.x * v0 + p4.y * v1;
                t = fmaf(p4.z, v2, t);
                t = fmaf(p4.w, v3, t);
                acc[r] += t;
            }
        }
    }

    #pragma unroll
    for (int step = 8; step >= 1; step >>= 1) {
        __syncthreads();
        if (warp >= step && warp < 2*step) {
            #pragma unroll
            for (int r = 0; r < ROWS; r++)
                sRed[(warp - step) * (ROWS*32) + r * 32 + lane] = acc[r];
        }
        __syncthreads();
        if (warp < step) {
            #pragma unroll
            for (int r = 0; r < ROWS; r++)
                acc[r] += sRed[warp * (ROWS*32) + r * 32 + lane];
        }
    }
    if (warp == 0) {
        #pragma unroll
        for (int r = 0; r < ROWS; r++)
            g_ctx[((size_t)(b * S_ + q0 + r)) * D_ + h * DH_ + lane] = acc[r];
    }
}

// ---------------------------------------------------------------------------
extern "C" void kernel_launch(void* const* d_in, const int* in_sizes, int n_in,
                              void* d_out, int out_size) {
    const float* q      = (const float*)d_in[0];
    const float* k      = (const float*)d_in[1];
    const float* v      = (const float*)d_in[2];
    const float* Wq     = (const float*)d_in[4];
    const float* bq     = (const float*)d_in[5];
    const float* Wv     = (const float*)d_in[6];
    const float* bv     = (const float*)d_in[7];
    const float* Wo     = (const float*)d_in[8];
    const float* bo     = (const float*)d_in[9];
    const float* gammas = (const float*)d_in[10];

    float* out    = (float*)d_out;                       // [B,S,D]
    float* scores = out + (size_t)B_ * S_ * D_;          // [B,H,S,S]

    float *Qp, *Kp, *Vp, *ctx;
    cudaGetSymbolAddress((void**)&Qp,  g_Qp);
    cudaGetSymbolAddress((void**)&Kp,  g_Kp);
    cudaGetSymbolAddress((void**)&Vp,  g_Vp);
    cudaGetSymbolAddress((void**)&ctx, g_ctx);

    cudaFuncSetAttribute(proj3_kernel, cudaFuncAttributeMaxDynamicSharedMemorySize, GS_TOTAL);
    cudaFuncSetAttribute(gemm_bias_kernel, cudaFuncAttributeMaxDynamicSharedMemorySize, GS_TOTAL);

    proj3_kernel<<<dim3(2, 64, 3), GT, GS_TOTAL>>>(q, k, v, Wq, bq, Wv, bv, Qp, Kp, Vp);

    cudaFuncSetAttribute(attn_kernel, cudaFuncAttributeMaxDynamicSharedMemorySize, SMEM_BYTES);
    attn_kernel<<<dim3(S_ / ROWS, BH_), THREADS, SMEM_BYTES>>>(gammas, scores);

    gemm_bias_kernel<<<dim3(2, 64), GT, GS_TOTAL>>>(ctx, Wo, bo, out);
}

// round 10
// speedup vs baseline: 1.4802x; 1.2765x over previous
#include <cuda_runtime.h>
#include <cuda_bf16.h>
#include <cuda_fp16.h>
#include <mma.h>
#include <math.h>
#include <cstdint>

using namespace nvcuda;

#define B_ 8
#define S_ 1024
#define D_ 256
#define H_ 8
#define DH_ 32
#define BH_ (B_*H_)
#define ROWS 16
#define SS_STRIDE 1028
#define THREADS 512
#define GT 256
#define KCH 32
#define LDA 40
#define LDC 132
#define GS_TOTAL (128 * LDC * 4)

// Scratch (device globals: no allocation allowed)
__device__ __half g_Qh[BH_*S_*DH_], g_Ql[BH_*S_*DH_];
__device__ __half g_Kh[BH_*S_*DH_], g_Kl[BH_*S_*DH_];
__device__ __half g_Vh[BH_*S_*DH_], g_Vl[BH_*S_*DH_];
__device__ float  g_ctx[B_*S_*D_];

// ---------------------------------------------------------------------------
// Tensor-core GEMM (wmma bf16 split 3-term): C = A @ W^T + bias
// mode 0: fp32 row-major out. mode 1: scaled fp16 hi/lo, head layout.
// ---------------------------------------------------------------------------
__device__ __forceinline__ void gemm_tc_body(
    const float* __restrict__ A, const float* __restrict__ W,
    const float* __restrict__ bias, float* __restrict__ Cf,
    __half* __restrict__ Ch, __half* __restrict__ Cl, int mode, float outScale)
{
    extern __shared__ char gsm[];
    __nv_bfloat16* sAhi = (__nv_bfloat16*)gsm;          // [128][LDA]
    __nv_bfloat16* sAlo = sAhi + 128 * LDA;
    __nv_bfloat16* sBhi = sAlo + 128 * LDA;
    __nv_bfloat16* sBlo = sBhi + 128 * LDA;
    float* sC = (float*)gsm;                             // reused after mainloop

    int tid = threadIdx.x;
    int warp = tid >> 5;
    int m0 = blockIdx.y * 128, n0 = blockIdx.x * 128;
    int mw = (warp >> 2) * 64;
    int nw = (warp & 3) * 32;

    wmma::fragment<wmma::accumulator, 16, 16, 16, float> acc[4][2];
    #pragma unroll
    for (int i = 0; i < 4; i++)
        #pragma unroll
        for (int j = 0; j < 2; j++)
            wmma::fill_fragment(acc[i][j], 0.0f);

    for (int kc = 0; kc < D_; kc += KCH) {
        __syncthreads();
        #pragma unroll
        for (int it = 0; it < 4; it++) {
            int idx = tid + it * GT;
            int r = idx >> 3, c4 = (idx & 7) << 2;
            float4 x = *(const float4*)&A[(size_t)(m0 + r) * D_ + kc + c4];
            __nv_bfloat16 hx = __float2bfloat16_rn(x.x);
            __nv_bfloat16 hy = __float2bfloat16_rn(x.y);
            __nv_bfloat16 hz = __float2bfloat16_rn(x.z);
            __nv_bfloat16 hw = __float2bfloat16_rn(x.w);
            *(__nv_bfloat162*)&sAhi[r*LDA + c4]     = __nv_bfloat162(hx, hy);
            *(__nv_bfloat162*)&sAhi[r*LDA + c4 + 2] = __nv_bfloat162(hz, hw);
            *(__nv_bfloat162*)&sAlo[r*LDA + c4] = __nv_bfloat162(
                __float2bfloat16_rn(x.x - __bfloat162float(hx)),
                __float2bfloat16_rn(x.y - __bfloat162float(hy)));
            *(__nv_bfloat162*)&sAlo[r*LDA + c4 + 2] = __nv_bfloat162(
                __float2bfloat16_rn(x.z - __bfloat162float(hz)),
                __float2bfloat16_rn(x.w - __bfloat162float(hw)));
        }
        #pragma unroll
        for (int it = 0; it < 4; it++) {
            int idx = tid + it * GT;
            int r = idx >> 3, c4 = (idx & 7) << 2;
            float4 x = *(const float4*)&W[(size_t)(n0 + r) * D_ + kc + c4];
            __nv_bfloat16 hx = __float2bfloat16_rn(x.x);
            __nv_bfloat16 hy = __float2bfloat16_rn(x.y);
            __nv_bfloat16 hz = __float2bfloat16_rn(x.z);
            __nv_bfloat16 hw = __float2bfloat16_rn(x.w);
            *(__nv_bfloat162*)&sBhi[r*LDA + c4]     = __nv_bfloat162(hx, hy);
            *(__nv_bfloat162*)&sBhi[r*LDA + c4 + 2] = __nv_bfloat162(hz, hw);
            *(__nv_bfloat162*)&sBlo[r*LDA + c4] = __nv_bfloat162(
                __float2bfloat16_rn(x.x - __bfloat162float(hx)),
                __float2bfloat16_rn(x.y - __bfloat162float(hy)));
            *(__nv_bfloat162*)&sBlo[r*LDA + c4 + 2] = __nv_bfloat162(
                __float2bfloat16_rn(x.z - __bfloat162float(hz)),
                __float2bfloat16_rn(x.w - __bfloat162float(hw)));
        }
        __syncthreads();

        #pragma unroll
        for (int kk = 0; kk < KCH; kk += 16) {
            wmma::fragment<wmma::matrix_a, 16, 16, 16, __nv_bfloat16, wmma::row_major> ah[4], al[4];
            wmma::fragment<wmma::matrix_b, 16, 16, 16, __nv_bfloat16, wmma::col_major> bh[2], bl[2];
            #pragma unroll
            for (int i = 0; i < 4; i++) {
                wmma::load_matrix_sync(ah[i], &sAhi[(mw + i*16) * LDA + kk], LDA);
                wmma::load_matrix_sync(al[i], &sAlo[(mw + i*16) * LDA + kk], LDA);
            }
            #pragma unroll
            for (int j = 0; j < 2; j++) {
                wmma::load_matrix_sync(bh[j], &sBhi[(nw + j*16) * LDA + kk], LDA);
                wmma::load_matrix_sync(bl[j], &sBlo[(nw + j*16) * LDA + kk], LDA);
            }
            #pragma unroll
            for (int i = 0; i < 4; i++)
                #pragma unroll
                for (int j = 0; j < 2; j++) {
                    wmma::mma_sync(acc[i][j], ah[i], bh[j], acc[i][j]);
                    wmma::mma_sync(acc[i][j], ah[i], bl[j], acc[i][j]);
                    wmma::mma_sync(acc[i][j], al[i], bh[j], acc[i][j]);
                }
        }
    }
    __syncthreads();

    #pragma unroll
    for (int i = 0; i < 4; i++)
        #pragma unroll
        for (int j = 0; j < 2; j++)
            wmma::store_matrix_sync(&sC[(mw + i*16) * LDC + nw + j*16],
                                    acc[i][j], LDC, wmma::mem_row_major);
    __syncthreads();

    #pragma unroll
    for (int it = 0; it < 16; it++) {
        int idx = tid + it * GT;
        int r = idx >> 5, c4 = (idx & 31) << 2;
        float4 v = *(const float4*)&sC[r * LDC + c4];
        int n = n0 + c4;
        v.x += bias[n]; v.y += bias[n+1]; v.z += bias[n+2]; v.w += bias[n+3];
        int m = m0 + r, bbat = m >> 10, ss = m & 1023;
        if (mode == 1) {
            v.x *= outScale; v.y *= outScale; v.z *= outScale; v.w *= outScale;
            int h = n >> 5, dh = n & 31;
            size_t base = (((size_t)(bbat * H_ + h)) * S_ + ss) * DH_ + dh;
            __half hx = __float2half_rn(v.x), hy = __float2half_rn(v.y);
            __half hz = __float2half_rn(v.z), hw = __float2half_rn(v.w);
            *(__half2*)&Ch[base]     = __halves2half2(hx, hy);
            *(__half2*)&Ch[base + 2] = __halves2half2(hz, hw);
            *(__half2*)&Cl[base] = __halves2half2(
                __float2half_rn(v.x - __half2float(hx)),
                __float2half_rn(v.y - __half2float(hy)));
            *(__half2*)&Cl[base + 2] = __halves2half2(
                __float2half_rn(v.z - __half2float(hz)),
                __float2half_rn(v.w - __half2float(hw)));
        } else {
            *(float4*)&Cf[(size_t)m * D_ + n] = v;
        }
    }
}

__global__ __launch_bounds__(GT) void proj3_kernel(
    const float* __restrict__ q, const float* __restrict__ k, const float* __restrict__ v,
    const float* __restrict__ Wq, const float* __restrict__ bq,
    const float* __restrict__ Wv, const float* __restrict__ bv,
    __half* Qh, __half* Ql, __half* Kh, __half* Kl, __half* Vh, __half* Vl)
{
    int z = blockIdx.z;
    const float* A = (z == 0) ? q : (z == 1) ? k : v;
    const float* W = (z == 2) ? Wv : Wq;
    const float* bias = (z == 2) ? bv : bq;
    __half* Ch = (z == 0) ? Qh : (z == 1) ? Kh : Vh;
    __half* Cl = (z == 0) ? Ql : (z == 1) ? Kl : Vl;
    float scale = (z == 0) ? 0.17677669529663688f : 1.0f;
    gemm_tc_body(A, W, bias, nullptr, Ch, Cl, 1, scale);
}

__global__ __launch_bounds__(GT) void gemm_bias_kernel(
    const float* __restrict__ A, const float* __restrict__ W,
    const float* __restrict__ bias, float* __restrict__ C)
{
    gemm_tc_body(A, W, bias, C, nullptr, nullptr, 0, 1.0f);
}

// ---------------------------------------------------------------------------
// Fused attention: per block = one (b,h) and 16 query rows, 512 threads.
// QK + PV on HMMA (fp16 3-term split), row phase fp32.
// smem byte layout:
//   sS fp32 [16][1028]                          [0, 65792)
//   union U @ 65792:
//     QK: sQh[16][40]h, sQl, sKh[256][40]h, sKl     (43520 B)
//     PV: sVh[128][40]h, sVl, sPh[16][136]h, sPl, sPart[16][256]f (45568 B)
// ---------------------------------------------------------------------------
#define U_OFF   65792
#define SQH_OFF (U_OFF)
#define SQL_OFF (U_OFF + 1280)
#define SKH_OFF (U_OFF + 2560)
#define SKL_OFF (U_OFF + 23040)
#define SVH_OFF (U_OFF)
#define SVL_OFF (U_OFF + 10240)
#define SPH_OFF (U_OFF + 20480)
#define SPL_OFF (U_OFF + 24832)
#define SPART_OFF (U_OFF + 29184)
#define SMEM_BYTES (U_OFF + 45568)

__global__ __launch_bounds__(THREADS, 2) void attn_kernel(
    const float* __restrict__ gammas, float* __restrict__ scores_out)
{
    extern __shared__ char sm[];
    float*  sS  = (float*)sm;
    __half* sQh = (__half*)(sm + SQH_OFF);
    __half* sQl = (__half*)(sm + SQL_OFF);
    __half* sKh = (__half*)(sm + SKH_OFF);
    __half* sKl = (__half*)(sm + SKL_OFF);
    __half* sVh = (__half*)(sm + SVH_OFF);
    __half* sVl = (__half*)(sm + SVL_OFF);
    __half* sPh = (__half*)(sm + SPH_OFF);
    __half* sPl = (__half*)(sm + SPL_OFF);
    float*  sPart = (float*)(sm + SPART_OFF);

    int tid = threadIdx.x;
    int lane = tid & 31, warp = tid >> 5;
    int bh = blockIdx.y;
    int q0 = blockIdx.x * ROWS;
    int h = bh & (H_ - 1);
    int b = bh >> 3;
    size_t hbase = (size_t)bh * S_ * DH_;

    // ---- stage Q hi/lo (pre-scaled in proj3) ----
    if (tid < 128) {
        int buf = tid >> 6, t = tid & 63;
        int r = t >> 2, s = t & 3;
        const __half* src = (buf ? g_Ql : g_Qh) + hbase + (size_t)(q0 + r) * DH_ + s * 8;
        __half* dst = (buf ? sQl : sQh) + r * 40 + s * 8;
        *(int4*)dst = *(const int4*)src;
    }
    __syncthreads();

    wmma::fragment<wmma::matrix_a, 16, 16, 16, __half, wmma::row_major> qh0, qh1, ql0, ql1;
    wmma::load_matrix_sync(qh0, sQh,      40);
    wmma::load_matrix_sync(qh1, sQh + 16, 40);
    wmma::load_matrix_sync(ql0, sQl,      40);
    wmma::load_matrix_sync(ql1, sQl + 16, 40);

    int nchQK = (q0 + 16 + 255) >> 8;
    // ---- QK^T via HMMA: chunk = 256 cols; warp -> one 16-col tile ----
    for (int ch = 0; ch < nchQK; ch++) {
        int jb = ch * 256;
        __syncthreads();
        for (int f = tid; f < 2048; f += THREADS) {
            int buf = f >> 10, rem = f & 1023;
            int j = rem >> 2, s = rem & 3;
            const __half* src = (buf ? g_Kl : g_Kh) + hbase + (size_t)(jb + j) * DH_ + s * 8;
            __half* dst = (buf ? sKl : sKh) + j * 40 + s * 8;
            *(int4*)dst = *(const int4*)src;
        }
        __syncthreads();
        int jn = jb + warp * 16;
        if (jn <= q0) {      // tile has at least one unmasked column
            wmma::fragment<wmma::matrix_b, 16, 16, 16, __half, wmma::col_major> kh0, kh1, kl0, kl1;
            wmma::load_matrix_sync(kh0, &sKh[(warp*16) * 40],      40);
            wmma::load_matrix_sync(kh1, &sKh[(warp*16) * 40 + 16], 40);
            wmma::load_matrix_sync(kl0, &sKl[(warp*16) * 40],      40);
            wmma::load_matrix_sync(kl1, &sKl[(warp*16) * 40 + 16], 40);
            wmma::fragment<wmma::accumulator, 16, 16, 16, float> sacc;
            wmma::fill_fragment(sacc, 0.0f);
            wmma::mma_sync(sacc, qh0, kh0, sacc);
            wmma::mma_sync(sacc, qh1, kh1, sacc);
            wmma::mma_sync(sacc, qh0, kl0, sacc);
            wmma::mma_sync(sacc, qh1, kl1, sacc);
            wmma::mma_sync(sacc, ql0, kh0, sacc);
            wmma::mma_sync(sacc, ql1, kh1, sacc);
            wmma::store_matrix_sync(&sS[jn], sacc, SS_STRIDE, wmma::mem_row_major);
        }
    }
    __syncthreads();

    // ---- row phase (1 row/warp): Z1, scan+decay, normalize+write ----
    {
        float gam = -fabsf(gammas[h]);
        int qg = q0 + warp;
        int L = qg + 1;
        float* row = sS + (size_t)warp * SS_STRIDE;

        float Z1 = 0.f;
        for (int j = lane * 4; j < L; j += 128) {
            float4 sv = *(const float4*)&row[j];
            if (j + 0 < L) Z1 += __expf(sv.x);
            if (j + 1 < L) Z1 += __expf(sv.y);
            if (j + 2 < L) Z1 += __expf(sv.z);
            if (j + 3 < L) Z1 += __expf(sv.w);
        }
        #pragma unroll
        for (int o = 16; o; o >>= 1) Z1 += __shfl_xor_sync(0xffffffffu, Z1, o);
        float invZ1 = __frcp_rn(Z1);

        float running = 0.f, Z2 = 0.f;
        int nb = (L + 127) >> 7;
        for (int bi = 0; bi < nb; bi++) {
            int j = bi * 128 + lane * 4;
            float4 sv = *(const float4*)&row[j];
            float e0 = (j + 0 < L) ? __expf(sv.x) : 0.f;
            float e1 = (j + 1 < L) ? __expf(sv.y) : 0.f;
            float e2 = (j + 2 < L) ? __expf(sv.z) : 0.f;
            float e3 = (j + 3 < L) ? __expf(sv.w) : 0.f;
            float p1 = e0 + e1, p2 = p1 + e2, p3 = p2 + e3;
            float c = p3;
            #pragma unroll
            for (int o = 1; o < 32; o <<= 1) {
                float t = __shfl_up_sync(0xffffffffu, c, o);
                if (lane >= o) c += t;
            }
            float excl = running + c - p3;
            running += __shfl_sync(0xffffffffu, c, 31);
            float4 out = {0.f, 0.f, 0.f, 0.f};
            if (j + 0 < L) {
                float rem = 1.f - (excl + e0) * invZ1;
                float dist = sqrtf(fmaxf(rem * (float)(qg - j), 0.f));
                float eff = fmaxf(__expf(gam * dist), 1e-5f);
                out.x = __expf(sv.x * eff); Z2 += out.x;
            }
            if (j + 1 < L) {
                float rem = 1.f - (excl + p1) * invZ1;
                float dist = sqrtf(fmaxf(rem * (float)(qg - j - 1), 0.f));
                float eff = fmaxf(__expf(gam * dist), 1e-5f);
                out.y = __expf(sv.y * eff); Z2 += out.y;
            }
            if (j + 2 < L) {
                float rem = 1.f - (excl + p2) * invZ1;
                float dist = sqrtf(fmaxf(rem * (float)(qg - j - 2), 0.f));
                float eff = fmaxf(__expf(gam * dist), 1e-5f);
                out.z = __expf(sv.z * eff); Z2 += out.z;
            }
            if (j + 3 < L) {
                float rem = 1.f - (excl + p3) * invZ1;
                float dist = sqrtf(fmaxf(rem * (float)(qg - j - 3), 0.f));
                float eff = fmaxf(__expf(gam * dist), 1e-5f);
                out.w = __expf(sv.w * eff); Z2 += out.w;
            }
            *(float4*)&row[j] = out;
        }
        #pragma unroll
        for (int o = 16; o; o >>= 1) Z2 += __shfl_xor_sync(0xffffffffu, Z2, o);
        float invZ2 = __frcp_rn(Z2);

        float* grow = scores_out + ((size_t)bh * S_ + qg) * S_;
        for (int j = lane * 4; j < S_; j += 128) {
            float4 pv = *(const float4*)&row[j];
            float4 p;
            p.x = (j + 0 < L) ? pv.x * invZ2 : 0.f;
            p.y = (j + 1 < L) ? pv.y * invZ2 : 0.f;
            p.z = (j + 2 < L) ? pv.z * invZ2 : 0.f;
            p.w = (j + 3 < L) ? pv.w * invZ2 : 0.f;
            *(float4*)&row[j] = p;
            __stcs((float4*)&grow[j], p);
        }
    }

    // ---- PV via HMMA: chunk = 128 js; warp = (kslot 0..7) x (ntile 0..1) ----
    int kslot = warp & 7, ntile = warp >> 3;
    wmma::fragment<wmma::accumulator, 16, 16, 16, float> accPV;
    wmma::fill_fragment(accPV, 0.0f);
    int nchPV = (q0 + 16 + 127) >> 7;
    for (int ch = 0; ch < nchPV; ch++) {
        int jb = ch * 128;
        __syncthreads();
        for (int f = tid; f < 1024; f += THREADS) {
            int buf = f >> 9, rem = f & 511;
            int j = rem >> 2, s = rem & 3;
            const __half* src = (buf ? g_Vl : g_Vh) + hbase + (size_t)(jb + j) * DH_ + s * 8;
            __half* dst = (buf ? sVl : sVh) + j * 40 + s * 8;
            *(int4*)dst = *(const int4*)src;
        }
        for (int idx = tid; idx < 2048; idx += THREADS) {
            int r = idx >> 7, c = idx & 127;
            float p = sS[(size_t)r * SS_STRIDE + jb + c];
            __half ph = __float2half_rn(p);
            sPh[r * 136 + c] = ph;
            sPl[r * 136 + c] = __float2half_rn(p - __half2float(ph));
        }
        __syncthreads();
        wmma::fragment<wmma::matrix_a, 16, 16, 16, __half, wmma::row_major> aph, apl;
        wmma::fragment<wmma::matrix_b, 16, 16, 16, __half, wmma::row_major> bvh, bvl;
        wmma::load_matrix_sync(aph, &sPh[kslot * 16], 136);
        wmma::load_matrix_sync(apl, &sPl[kslot * 16], 136);
        wmma::load_matrix_sync(bvh, &sVh[(kslot * 16) * 40 + ntile * 16], 40);
        wmma::load_matrix_sync(bvl, &sVl[(kslot * 16) * 40 + ntile * 16], 40);
        wmma::mma_sync(accPV, aph, bvh, accPV);
        wmma::mma_sync(accPV, aph, bvl, accPV);
        wmma::mma_sync(accPV, apl, bvh, accPV);
    }
    wmma::store_matrix_sync(&sPart[warp * 256], accPV, 16, wmma::mem_row_major);
    __syncthreads();

    // reduce 8 k-slot partials per ntile; warps 0,1 = ntile 0,1
    if (warp < 2) {
        for (int e = lane; e < 256; e += 32) {
            float s = 0.f;
            #pragma unroll
            for (int k = 0; k < 8; k++)
                s += sPart[(warp * 8 + k) * 256 + e];
            int r = e >> 4, c = e & 15;
            g_ctx[((size_t)(b * S_ + q0 + r)) * D_ + h * DH_ + warp * 16 + c] = s;
        }
    }
}

// ---------------------------------------------------------------------------
extern "C" void kernel_launch(void* const* d_in, const int* in_sizes, int n_in,
                              void* d_out, int out_size) {
    const float* q      = (const float*)d_in[0];
    const float* k      = (const float*)d_in[1];
    const float* v      = (const float*)d_in[2];
    const float* Wq     = (const float*)d_in[4];
    const float* bq     = (const float*)d_in[5];
    const float* Wv     = (const float*)d_in[6];
    const float* bv     = (const float*)d_in[7];
    const float* Wo     = (const float*)d_in[8];
    const float* bo     = (const float*)d_in[9];
    const float* gammas = (const float*)d_in[10];

    float* out    = (float*)d_out;                       // [B,S,D]
    float* scores = out + (size_t)B_ * S_ * D_;          // [B,H,S,S]

    __half *Qh, *Ql, *Kh, *Kl, *Vh, *Vl;
    float* ctx;
    cudaGetSymbolAddress((void**)&Qh, g_Qh);
    cudaGetSymbolAddress((void**)&Ql, g_Ql);
    cudaGetSymbolAddress((void**)&Kh, g_Kh);
    cudaGetSymbolAddress((void**)&Kl, g_Kl);
    cudaGetSymbolAddress((void**)&Vh, g_Vh);
    cudaGetSymbolAddress((void**)&Vl, g_Vl);
    cudaGetSymbolAddress((void**)&ctx, g_ctx);

    cudaFuncSetAttribute(proj3_kernel, cudaFuncAttributeMaxDynamicSharedMemorySize, GS_TOTAL);
    cudaFuncSetAttribute(gemm_bias_kernel, cudaFuncAttributeMaxDynamicSharedMemorySize, GS_TOTAL);

    proj3_kernel<<<dim3(2, 64, 3), GT, GS_TOTAL>>>(q, k, v, Wq, bq, Wv, bv,
                                                   Qh, Ql, Kh, Kl, Vh, Vl);

    cudaFuncSetAttribute(attn_kernel, cudaFuncAttributeMaxDynamicSharedMemorySize, SMEM_BYTES);
    attn_kernel<<<dim3(S_ / ROWS, BH_), THREADS, SMEM_BYTES>>>(gammas, scores);

    gemm_bias_kernel<<<dim3(2, 64), GT, GS_TOTAL>>>(ctx, Wo, bo, out);
}